// round 12
// baseline (speedup 1.0000x reference)
#include <cuda_runtime.h>
#include <cuda_bf16.h>
#include <stdint.h>
#include <math.h>

#define B_   2
#define T_   2048
#define C_   1024
#define H_   16
#define DK_  64
#define HD_  1024   // H_*DK_
#define M_   4096   // B_*T_
#define KDIM 1024
#define NCH  16     // KDIM / 64

// ---------------- scratch (no allocation allowed) ----------------
__device__ __nv_bfloat16 g_qhi[(size_t)B_*H_*T_*DK_];
__device__ __nv_bfloat16 g_qlo[(size_t)B_*H_*T_*DK_];
__device__ __nv_bfloat16 g_khi[(size_t)B_*H_*T_*DK_];
__device__ __nv_bfloat16 g_klo[(size_t)B_*H_*T_*DK_];
__device__ __nv_bfloat16 g_vhi[(size_t)B_*H_*T_*DK_];
__device__ __nv_bfloat16 g_vlo[(size_t)B_*H_*T_*DK_];
__device__ __nv_bfloat16 g_ohi[(size_t)M_*HD_];
__device__ __nv_bfloat16 g_olo[(size_t)M_*HD_];
__device__ __nv_bfloat16 g_xhi[(size_t)M_*KDIM];
__device__ __nv_bfloat16 g_xlo[(size_t)M_*KDIM];
__device__ __nv_bfloat16 g_whi[(size_t)4*KDIM*HD_];   // transposed [n][k]; z: q,k,v,o
__device__ __nv_bfloat16 g_wlo[(size_t)4*KDIM*HD_];

// ---------------- helpers ----------------
__device__ __forceinline__ uint32_t smem_u32(const void* p) {
    uint32_t a;
    asm("{ .reg .u64 t; cvta.to.shared.u64 t, %1; cvt.u32.u64 %0, t; }"
        : "=r"(a) : "l"(p));
    return a;
}
#define SW128(o) ((uint32_t)(o) ^ ((((uint32_t)(o)) >> 3) & 0x70u))

__device__ __forceinline__ void ldm_x4(uint32_t* r, uint32_t addr) {
    asm volatile("ldmatrix.sync.aligned.m8n8.x4.shared.b16 {%0,%1,%2,%3}, [%4];"
                 : "=r"(r[0]), "=r"(r[1]), "=r"(r[2]), "=r"(r[3]) : "r"(addr));
}
__device__ __forceinline__ void ldm_x4_trans(uint32_t* r, uint32_t addr) {
    asm volatile("ldmatrix.sync.aligned.m8n8.x4.trans.shared.b16 {%0,%1,%2,%3}, [%4];"
                 : "=r"(r[0]), "=r"(r[1]), "=r"(r[2]), "=r"(r[3]) : "r"(addr));
}

__device__ __forceinline__ void mma_bf16(float* c, const uint32_t* a,
                                         uint32_t b0, uint32_t b1) {
    asm volatile(
        "mma.sync.aligned.m16n8k16.row.col.f32.bf16.bf16.f32 "
        "{%0,%1,%2,%3}, {%4,%5,%6,%7}, {%8,%9}, {%0,%1,%2,%3};"
        : "+f"(c[0]), "+f"(c[1]), "+f"(c[2]), "+f"(c[3])
        : "r"(a[0]), "r"(a[1]), "r"(a[2]), "r"(a[3]), "r"(b0), "r"(b1));
}

__device__ __forceinline__ void cp_async16(uint32_t dst, const void* src) {
    asm volatile("cp.async.cg.shared.global [%0], [%1], 16;"
                 :: "r"(dst), "l"(src));
}
#define CP_COMMIT() asm volatile("cp.async.commit_group;" ::: "memory")
#define CP_WAIT0()  asm volatile("cp.async.wait_group 0;" ::: "memory")
#define CP_WAIT1()  asm volatile("cp.async.wait_group 1;" ::: "memory")

// rounding split (prep + gemm epilogue): exact-ish, lo rounds
__device__ __forceinline__ void split2(float a, float b, uint32_t& hi, uint32_t& lo) {
    __nv_bfloat16 ah = __float2bfloat16(a);
    __nv_bfloat16 bh = __float2bfloat16(b);
    __nv_bfloat16 al = __float2bfloat16(a - __bfloat162float(ah));
    __nv_bfloat16 bl = __float2bfloat16(b - __bfloat162float(bh));
    uint16_t ahb = *(uint16_t*)&ah, bhb = *(uint16_t*)&bh;
    uint16_t alb = *(uint16_t*)&al, blb = *(uint16_t*)&bl;
    hi = (uint32_t)ahb | ((uint32_t)bhb << 16);
    lo = (uint32_t)alb | ((uint32_t)blb << 16);
}

// fast Dekker-style split (truncation hi, single packed cvt for lo) — hot paths
__device__ __forceinline__ void fast_split2(float a, float b, uint32_t& hi, uint32_t& lo) {
    uint32_t ua = __float_as_uint(a) & 0xFFFF0000u;
    uint32_t ub = __float_as_uint(b) & 0xFFFF0000u;
    hi = __byte_perm(ua, ub, 0x7632);          // low16 = bf16(a), high16 = bf16(b)
    float la = a - __uint_as_float(ua);
    float lb = b - __uint_as_float(ub);
    asm("cvt.rn.bf16x2.f32 %0, %1, %2;" : "=r"(lo) : "f"(lb), "f"(la));
}

// ---------------- prep: merged convert + transpose (one launch) -----------
// grid (32, 32, 5): z=0..3 -> transpose W_z [k][n] fp32 -> [n][k] bf16 hi/lo
//                   z=4    -> elementwise convert x -> bf16 hi/lo
__global__ void __launch_bounds__(256)
prep_kernel(const float* __restrict__ x,
            const float* __restrict__ Wq, const float* __restrict__ Wk,
            const float* __restrict__ Wv, const float* __restrict__ Wo,
            __nv_bfloat16* __restrict__ xhi, __nv_bfloat16* __restrict__ xlo,
            __nv_bfloat16* __restrict__ whi, __nv_bfloat16* __restrict__ wlo)
{
    const int z = blockIdx.z;
    if (z == 4) {
        int base = (blockIdx.y * 32 + blockIdx.x) * 1024 + threadIdx.x;
#pragma unroll
        for (int p = 0; p < 4; p++) {
            int i = base + p * 256;
            float4 v = ((const float4*)x)[i];
            uint32_t h0, l0, h1, l1;
            split2(v.x, v.y, h0, l0);
            split2(v.z, v.w, h1, l1);
            ((uint2*)xhi)[i] = make_uint2(h0, h1);
            ((uint2*)xlo)[i] = make_uint2(l0, l1);
        }
        return;
    }
    __shared__ float t[32][33];
    const float* W = (z == 0) ? Wq : (z == 1) ? Wk : (z == 2) ? Wv : Wo;
    __nv_bfloat16* ho  = whi + (size_t)z * KDIM * HD_;
    __nv_bfloat16* lo_ = wlo + (size_t)z * KDIM * HD_;

    const int k0 = blockIdx.x * 32;
    const int n0 = blockIdx.y * 32;
    const int tx = threadIdx.x & 31, ty = threadIdx.x >> 5;

#pragma unroll
    for (int r = 0; r < 4; r++)
        t[ty + r * 8][tx] = W[(size_t)(k0 + ty + r * 8) * HD_ + n0 + tx];
    __syncthreads();
#pragma unroll
    for (int r = 0; r < 4; r++) {
        float f = t[tx][ty + r * 8];
        __nv_bfloat16 h = __float2bfloat16(f);
        __nv_bfloat16 l = __float2bfloat16(f - __bfloat162float(h));
        size_t o = (size_t)(n0 + ty + r * 8) * KDIM + k0 + tx;
        ho[o] = h;
        lo_[o] = l;
    }
}

// ---------------- bf16x3 mma.sync GEMM (proven core, staged epilogue) -----
#define SM_BUF 65536u
#define SM_AHI 0u
#define SM_ALO 16384u
#define SM_BHI 32768u
#define SM_BLO 49152u
#define SM_TOTAL 131072

__device__ __forceinline__ void load_chunk(
    uint32_t sbuf,
    const __nv_bfloat16* __restrict__ Ahi, const __nv_bfloat16* __restrict__ Alo,
    const __nv_bfloat16* __restrict__ Bhi, const __nv_bfloat16* __restrict__ Blo,
    int bRow, int bCol, int ch, int tid)
{
#pragma unroll
    for (int p = 0; p < 2; p++) {
        int idx = p * 512 + tid;
        int r = idx >> 3;
        int c = idx & 7;
        uint32_t off = SW128(r * 128 + c * 16);
        cp_async16(sbuf + SM_AHI + off, Ahi + (size_t)(bRow * 128 + r) * KDIM + ch * 64 + c * 8);
        cp_async16(sbuf + SM_ALO + off, Alo + (size_t)(bRow * 128 + r) * KDIM + ch * 64 + c * 8);
        cp_async16(sbuf + SM_BHI + off, Bhi + (size_t)(bCol * 128 + r) * KDIM + ch * 64 + c * 8);
        cp_async16(sbuf + SM_BLO + off, Blo + (size_t)(bCol * 128 + r) * KDIM + ch * 64 + c * 8);
    }
}

__global__ void __launch_bounds__(512, 1)
gemm_bf16_kernel(const __nv_bfloat16* __restrict__ Ahi,
                 const __nv_bfloat16* __restrict__ Alo,
                 __nv_bfloat16* __restrict__ S0h, __nv_bfloat16* __restrict__ S0l,
                 __nv_bfloat16* __restrict__ S1h, __nv_bfloat16* __restrict__ S1l,
                 __nv_bfloat16* __restrict__ S2h, __nv_bfloat16* __restrict__ S2l,
                 float* __restrict__ Cout,
                 int wzoff, int scatter)
{
    extern __shared__ char gsm[];
    const uint32_t sb = smem_u32(gsm);

    const int tid  = threadIdx.x;
    const int wid  = tid >> 5;
    const int lane = tid & 31;
    const int bRow = blockIdx.y;
    const int bCol = blockIdx.x;
    const int z    = blockIdx.z;

    const __nv_bfloat16* Bhi = g_whi + (size_t)(wzoff + z) * KDIM * HD_;
    const __nv_bfloat16* Blo = g_wlo + (size_t)(wzoff + z) * KDIM * HD_;

    const int m0 = (wid >> 2) * 32;
    const int n0 = (wid & 3) * 32;

    float acc[2][4][4];
#pragma unroll
    for (int mt = 0; mt < 2; mt++)
#pragma unroll
        for (int j = 0; j < 4; j++)
#pragma unroll
            for (int r = 0; r < 4; r++) acc[mt][j][r] = 0.0f;

    load_chunk(sb, Ahi, Alo, Bhi, Blo, bRow, bCol, 0, tid);
    CP_COMMIT();
    load_chunk(sb + SM_BUF, Ahi, Alo, Bhi, Blo, bRow, bCol, 1, tid);
    CP_COMMIT();

    for (int ch = 0; ch < NCH; ch++) {
        const uint32_t sbuf = sb + (ch & 1) * SM_BUF;
        if (ch == NCH - 1) CP_WAIT0(); else CP_WAIT1();
        __syncthreads();

#pragma unroll
        for (int ks = 0; ks < 4; ks++) {
            const uint32_t colb = ks * 32 + (lane >> 4) * 16;
            uint32_t ahi[2][4], alo[2][4], bhi4[2][4], blo4[2][4];
#pragma unroll
            for (int mt = 0; mt < 2; mt++) {
                uint32_t roff = (uint32_t)(m0 + mt * 16 + (lane & 15)) * 128 + colb;
                ldm_x4(ahi[mt], sbuf + SM_AHI + SW128(roff));
                ldm_x4(alo[mt], sbuf + SM_ALO + SW128(roff));
            }
#pragma unroll
            for (int nt = 0; nt < 2; nt++) {
                uint32_t roff = (uint32_t)(n0 + nt * 16 + (lane & 15)) * 128 + colb;
                ldm_x4(bhi4[nt], sbuf + SM_BHI + SW128(roff));
                ldm_x4(blo4[nt], sbuf + SM_BLO + SW128(roff));
            }
#pragma unroll
            for (int mt = 0; mt < 2; mt++)
#pragma unroll
                for (int j = 0; j < 4; j++)
                    mma_bf16(acc[mt][j], ahi[mt], bhi4[j >> 1][j & 1], bhi4[j >> 1][(j & 1) + 2]);
#pragma unroll
            for (int mt = 0; mt < 2; mt++)
#pragma unroll
                for (int j = 0; j < 4; j++)
                    mma_bf16(acc[mt][j], ahi[mt], blo4[j >> 1][j & 1], blo4[j >> 1][(j & 1) + 2]);
#pragma unroll
            for (int mt = 0; mt < 2; mt++)
#pragma unroll
                for (int j = 0; j < 4; j++)
                    mma_bf16(acc[mt][j], alo[mt], bhi4[j >> 1][j & 1], bhi4[j >> 1][(j & 1) + 2]);
        }
        __syncthreads();
        if (ch + 2 < NCH) {
            load_chunk(sbuf, Ahi, Alo, Bhi, Blo, bRow, bCol, ch + 2, tid);
            CP_COMMIT();
        }
    }

    if (scatter) {
        // ---- staged epilogue: smem bf16 hi/lo -> coalesced per-head blocks ----
        uint16_t* Dh = (uint16_t*)gsm;            // [128][128]
        uint16_t* Dl = (uint16_t*)(gsm + 32768);  // [128][128]
        const float sc = (z == 0) ? 8.0f : 1.0f;  // fold sqrt(dk) into q
#pragma unroll
        for (int mt = 0; mt < 2; mt++)
#pragma unroll
            for (int j = 0; j < 4; j++)
#pragma unroll
                for (int half = 0; half < 2; half++) {
                    int lrow = m0 + mt * 16 + (lane >> 2) + half * 8;
                    int lcol = n0 + j * 8 + (lane & 3) * 2;
                    uint32_t hi, lo;
                    split2(acc[mt][j][half * 2] * sc, acc[mt][j][half * 2 + 1] * sc, hi, lo);
                    *(uint32_t*)(Dh + lrow * 128 + lcol) = hi;
                    *(uint32_t*)(Dl + lrow * 128 + lcol) = lo;
                }
        __syncthreads();

        __nv_bfloat16* Gh = (z == 0) ? S0h : (z == 1) ? S1h : S2h;
        __nv_bfloat16* Gl = (z == 0) ? S0l : (z == 1) ? S1l : S2l;
        const int b  = bRow >> 4;
        const int t0 = (bRow & 15) * 128;
#pragma unroll
        for (int hh = 0; hh < 2; hh++) {
            int h = bCol * 2 + hh;
            size_t base = ((size_t)(b * H_ + h) * T_ + t0) * DK_;
#pragma unroll
            for (int p = 0; p < 2; p++) {
                int idx = p * 512 + tid;       // 0..1023
                int r = idx >> 3, c = idx & 7;
                *(uint4*)(Gh + base + r * 64 + c * 8) =
                    *(const uint4*)(Dh + r * 128 + hh * 64 + c * 8);
                *(uint4*)(Gl + base + r * 64 + c * 8) =
                    *(const uint4*)(Dl + r * 128 + hh * 64 + c * 8);
            }
        }
    } else {
        // fp32 output (final projection)
#pragma unroll
        for (int mt = 0; mt < 2; mt++)
#pragma unroll
            for (int j = 0; j < 4; j++) {
                int row = bRow * 128 + m0 + mt * 16 + (lane >> 2);
                int col = bCol * 128 + n0 + j * 8 + (lane & 3) * 2;
#pragma unroll
                for (int half = 0; half < 2; half++) {
                    int rr = row + half * 8;
                    *(float2*)(Cout + (size_t)rr * HD_ + col) =
                        make_float2(acc[mt][j][half * 2], acc[mt][j][half * 2 + 1]);
                }
            }
    }
}

// ---------------- flash attention on mma.sync (bf16x3) ----------------
#define SM_QHI 0u
#define SM_QLO 16384u
#define SM_KV  32768u
#define KV_KHI 0u
#define KV_KLO 8192u
#define KV_VHI 16384u
#define KV_VLO 24576u
#define KV_STRIDE 32768u
#define FSM_TOTAL 98304

__device__ __forceinline__ void load_kv(
    uint32_t kvbuf, const __nv_bfloat16* kh, const __nv_bfloat16* kl,
    const __nv_bfloat16* vh, const __nv_bfloat16* vl, int j0, int tid)
{
#pragma unroll
    for (int p = 0; p < 2; p++) {
        int idx = p * 256 + tid;
        int r = idx >> 3;             // 0..63
        int c = idx & 7;
        uint32_t off = SW128(r * 128 + c * 16);
        size_t src = (size_t)(j0 + r) * DK_ + c * 8;
        cp_async16(kvbuf + KV_KHI + off, kh + src);
        cp_async16(kvbuf + KV_KLO + off, kl + src);
        cp_async16(kvbuf + KV_VHI + off, vh + src);
        cp_async16(kvbuf + KV_VLO + off, vl + src);
    }
}

__global__ void __launch_bounds__(256, 2)
flash_mma_kernel(const __nv_bfloat16* __restrict__ qhi, const __nv_bfloat16* __restrict__ qlo,
                 const __nv_bfloat16* __restrict__ khi, const __nv_bfloat16* __restrict__ klo,
                 const __nv_bfloat16* __restrict__ vhi, const __nv_bfloat16* __restrict__ vlo,
                 __nv_bfloat16* __restrict__ ohi, __nv_bfloat16* __restrict__ olo)
{
    extern __shared__ char fsm[];
    const uint32_t sb = smem_u32(fsm);
    const int tid  = threadIdx.x;
    const int w    = tid >> 5;
    const int lane = tid & 31;
    const int qt   = (gridDim.x - 1) - blockIdx.x;   // heavy tiles first
    const int bh   = blockIdx.y;
    const int i0   = qt * 128;

    const __nv_bfloat16* qh = qhi + (size_t)bh * T_ * DK_;
    const __nv_bfloat16* ql = qlo + (size_t)bh * T_ * DK_;
    const __nv_bfloat16* kh = khi + (size_t)bh * T_ * DK_;
    const __nv_bfloat16* kl = klo + (size_t)bh * T_ * DK_;
    const __nv_bfloat16* vh = vhi + (size_t)bh * T_ * DK_;
    const __nv_bfloat16* vl = vlo + (size_t)bh * T_ * DK_;

    // load Q tile once (128 rows x 64 d, hi+lo)
#pragma unroll
    for (int p = 0; p < 4; p++) {
        int idx = p * 256 + tid;
        int r = idx >> 3;             // 0..127
        int c = idx & 7;
        uint32_t off = SW128(r * 128 + c * 16);
        size_t src = (size_t)(i0 + r) * DK_ + c * 8;
        cp_async16(sb + SM_QHI + off, qh + src);
        cp_async16(sb + SM_QLO + off, ql + src);
    }
    CP_COMMIT();

    const int nkt = 2 * (qt + 1);     // 64-key tiles
    load_kv(sb + SM_KV, kh, kl, vh, vl, 0, tid);
    CP_COMMIT();
    if (nkt > 1) {
        load_kv(sb + SM_KV + KV_STRIDE, kh, kl, vh, vl, 64, tid);
        CP_COMMIT();
    }

    float m_i[2] = {-1e30f, -1e30f};
    float l_i[2] = {0.0f, 0.0f};
    float o_acc[8][4];
#pragma unroll
    for (int f = 0; f < 8; f++)
#pragma unroll
        for (int r = 0; r < 4; r++) o_acc[f][r] = 0.0f;

    const int row0 = i0 + w * 16 + (lane >> 2);   // global q row (half 0)

    for (int jt = 0; jt < nkt; jt++) {
        const uint32_t kvbuf = sb + SM_KV + (uint32_t)(jt & 1) * KV_STRIDE;
        const int j0 = jt * 64;
        if (jt + 1 < nkt) CP_WAIT1(); else CP_WAIT0();
        __syncthreads();

        // ---- S = Q K^T : m16 x n64, 4 k16 steps, bf16x3 ----
        float s[8][4];
#pragma unroll
        for (int f = 0; f < 8; f++)
#pragma unroll
            for (int r = 0; r < 4; r++) s[f][r] = 0.0f;

#pragma unroll
        for (int ks = 0; ks < 4; ks++) {
            const uint32_t colb = ks * 32 + (lane >> 4) * 16;
            uint32_t aqh[4], aql[4];
            uint32_t roff = (uint32_t)(w * 16 + (lane & 15)) * 128 + colb;
            ldm_x4(aqh, sb + SM_QHI + SW128(roff));
            ldm_x4(aql, sb + SM_QLO + SW128(roff));
#pragma unroll
            for (int nt = 0; nt < 4; nt++) {
                uint32_t kh4[4], kl4[4];
                uint32_t noff = (uint32_t)(nt * 16 + (lane & 15)) * 128 + colb;
                ldm_x4(kh4, kvbuf + KV_KHI + SW128(noff));
                ldm_x4(kl4, kvbuf + KV_KLO + SW128(noff));
#pragma unroll
                for (int h = 0; h < 2; h++) {
                    int f = nt * 2 + h;
                    mma_bf16(s[f], aqh, kh4[h], kh4[h + 2]);
                    mma_bf16(s[f], aqh, kl4[h], kl4[h + 2]);
                    mma_bf16(s[f], aql, kh4[h], kh4[h + 2]);
                }
            }
        }

        // ---- causal mask (only tiles at/after the diagonal) ----
        if (j0 >= i0) {
#pragma unroll
            for (int f = 0; f < 8; f++) {
                int colg = j0 + f * 8 + (lane & 3) * 2;
                if (colg     > row0)     s[f][0] = -1e30f;
                if (colg + 1 > row0)     s[f][1] = -1e30f;
                if (colg     > row0 + 8) s[f][2] = -1e30f;
                if (colg + 1 > row0 + 8) s[f][3] = -1e30f;
            }
        }

        // ---- online softmax (rows row0, row0+8) ----
#pragma unroll
        for (int half = 0; half < 2; half++) {
            float mn = -1e30f;
#pragma unroll
            for (int f = 0; f < 8; f++)
                mn = fmaxf(mn, fmaxf(s[f][half * 2], s[f][half * 2 + 1]));
            mn = fmaxf(mn, __shfl_xor_sync(0xffffffffu, mn, 1));
            mn = fmaxf(mn, __shfl_xor_sync(0xffffffffu, mn, 2));

            float mnew = fmaxf(m_i[half], mn);
            float corr = __expf(m_i[half] - mnew);
            m_i[half] = mnew;

            float rs = 0.0f;
#pragma unroll
            for (int f = 0; f < 8; f++) {
                float p0 = __expf(s[f][half * 2]     - mnew);
                float p1 = __expf(s[f][half * 2 + 1] - mnew);
                s[f][half * 2]     = p0;
                s[f][half * 2 + 1] = p1;
                rs += p0 + p1;
            }
            rs += __shfl_xor_sync(0xffffffffu, rs, 1);
            rs += __shfl_xor_sync(0xffffffffu, rs, 2);

            l_i[half] = l_i[half] * corr + rs;
#pragma unroll
            for (int f = 0; f < 8; f++) {
                o_acc[f][half * 2]     *= corr;
                o_acc[f][half * 2 + 1] *= corr;
            }
        }

        // ---- O += P V : 4 k16 steps over keys, bf16x3 (fast split) ----
#pragma unroll
        for (int ks = 0; ks < 4; ks++) {
            uint32_t ph[4], pl[4];
            fast_split2(s[2 * ks][0],     s[2 * ks][1],     ph[0], pl[0]);
            fast_split2(s[2 * ks][2],     s[2 * ks][3],     ph[1], pl[1]);
            fast_split2(s[2 * ks + 1][0], s[2 * ks + 1][1], ph[2], pl[2]);
            fast_split2(s[2 * ks + 1][2], s[2 * ks + 1][3], ph[3], pl[3]);
#pragma unroll
            for (int dt = 0; dt < 4; dt++) {
                uint32_t vh4[4], vl4[4];
                uint32_t voff = (uint32_t)(ks * 16 + (lane & 15)) * 128
                              + dt * 32 + (lane >> 4) * 16;
                ldm_x4_trans(vh4, kvbuf + KV_VHI + SW128(voff));
                ldm_x4_trans(vl4, kvbuf + KV_VLO + SW128(voff));
#pragma unroll
                for (int h = 0; h < 2; h++) {
                    int f = dt * 2 + h;
                    mma_bf16(o_acc[f], ph, vh4[h * 2], vh4[h * 2 + 1]);
                    mma_bf16(o_acc[f], ph, vl4[h * 2], vl4[h * 2 + 1]);
                    mma_bf16(o_acc[f], pl, vh4[h * 2], vh4[h * 2 + 1]);
                }
            }
        }
        __syncthreads();
        if (jt + 2 < nkt) {
            load_kv(kvbuf, kh, kl, vh, vl, (jt + 2) * 64, tid);
            CP_COMMIT();
        }
    }

    // ---- staged O epilogue: smem bf16 hi/lo -> coalesced rows ----
    {
        uint16_t* Oh = (uint16_t*)fsm;            // [128][64]
        uint16_t* Ol = (uint16_t*)(fsm + 16384);  // [128][64]
        const float inv0 = 1.0f / l_i[0];
        const float inv1 = 1.0f / l_i[1];
        const int lr0 = w * 16 + (lane >> 2);
#pragma unroll
        for (int f = 0; f < 8; f++) {
            int d = f * 8 + (lane & 3) * 2;
            uint32_t hi, lo;
            fast_split2(o_acc[f][0] * inv0, o_acc[f][1] * inv0, hi, lo);
            *(uint32_t*)(Oh + lr0 * 64 + d) = hi;
            *(uint32_t*)(Ol + lr0 * 64 + d) = lo;
            fast_split2(o_acc[f][2] * inv1, o_acc[f][3] * inv1, hi, lo);
            *(uint32_t*)(Oh + (lr0 + 8) * 64 + d) = hi;
            *(uint32_t*)(Ol + (lr0 + 8) * 64 + d) = lo;
        }
        __syncthreads();

        const int b = bh >> 4, h = bh & 15;
        size_t base = ((size_t)(b * T_ + i0)) * HD_ + h * 64;
#pragma unroll
        for (int p = 0; p < 4; p++) {
            int idx = p * 256 + tid;      // 0..1023
            int r = idx >> 3, c = idx & 7;
            *(uint4*)(ohi + base + (size_t)r * HD_ + c * 8) =
                *(const uint4*)(Oh + r * 64 + c * 8);
            *(uint4*)(olo + base + (size_t)r * HD_ + c * 8) =
                *(const uint4*)(Ol + r * 64 + c * 8);
        }
    }
}

// ---------------- launch ----------------
extern "C" void kernel_launch(void* const* d_in, const int* in_sizes, int n_in,
                              void* d_out, int out_size)
{
    const float* x  = (const float*)d_in[0];
    const float* qm = (const float*)d_in[1];
    const float* km = (const float*)d_in[2];
    const float* vm = (const float*)d_in[3];
    const float* wm = (const float*)d_in[4];
    float* out = (float*)d_out;

    __nv_bfloat16 *qhi, *qlo, *khi, *klo, *vhi, *vlo, *ohi, *olo, *xhi, *xlo, *whi, *wlo;
    cudaGetSymbolAddress((void**)&qhi, g_qhi);
    cudaGetSymbolAddress((void**)&qlo, g_qlo);
    cudaGetSymbolAddress((void**)&khi, g_khi);
    cudaGetSymbolAddress((void**)&klo, g_klo);
    cudaGetSymbolAddress((void**)&vhi, g_vhi);
    cudaGetSymbolAddress((void**)&vlo, g_vlo);
    cudaGetSymbolAddress((void**)&ohi, g_ohi);
    cudaGetSymbolAddress((void**)&olo, g_olo);
    cudaGetSymbolAddress((void**)&xhi, g_xhi);
    cudaGetSymbolAddress((void**)&xlo, g_xlo);
    cudaGetSymbolAddress((void**)&whi, g_whi);
    cudaGetSymbolAddress((void**)&wlo, g_wlo);

    cudaFuncSetAttribute(gemm_bf16_kernel, cudaFuncAttributeMaxDynamicSharedMemorySize, SM_TOTAL);
    cudaFuncSetAttribute(flash_mma_kernel, cudaFuncAttributeMaxDynamicSharedMemorySize, FSM_TOTAL);

    // merged prep: x convert + 4 weight transposes in one launch
    dim3 pGrid(32, 32, 5);
    prep_kernel<<<pGrid, 256>>>(x, qm, km, vm, wm, xhi, xlo, whi, wlo);

    // fused QKV projection -> bf16 hi/lo splits in [B,H,T,DK] (q pre-scaled x8)
    dim3 qkvGrid(HD_ / 128, M_ / 128, 3);
    gemm_bf16_kernel<<<qkvGrid, 512, SM_TOTAL>>>(
        xhi, xlo, qhi, qlo, khi, klo, vhi, vlo, (float*)0, 0, 1);

    // tensor-core causal flash -> bf16 hi/lo O in [B,T,H*DK]
    dim3 flashGrid(T_ / 128, B_ * H_);
    flash_mma_kernel<<<flashGrid, 256, FSM_TOTAL>>>(
        qhi, qlo, khi, klo, vhi, vlo, ohi, olo);

    // output projection (fp32 out)
    dim3 oGrid(HD_ / 128, M_ / 128, 1);
    gemm_bf16_kernel<<<oGrid, 512, SM_TOTAL>>>(
        ohi, olo, (__nv_bfloat16*)0, (__nv_bfloat16*)0, (__nv_bfloat16*)0,
        (__nv_bfloat16*)0, (__nv_bfloat16*)0, (__nv_bfloat16*)0, out, 3, 0);
}

// round 16
// speedup vs baseline: 1.0929x; 1.0929x over previous
#include <cuda_runtime.h>
#include <cuda_bf16.h>
#include <stdint.h>
#include <math.h>

#define B_   2
#define T_   2048
#define C_   1024
#define H_   16
#define DK_  64
#define HD_  1024   // H_*DK_
#define M_   4096   // B_*T_
#define KDIM 1024
#define NCH  16     // KDIM / 64

// ---------------- scratch (no allocation allowed) ----------------
__device__ __nv_bfloat16 g_qhi[(size_t)B_*H_*T_*DK_];
__device__ __nv_bfloat16 g_qlo[(size_t)B_*H_*T_*DK_];
__device__ __nv_bfloat16 g_khi[(size_t)B_*H_*T_*DK_];
__device__ __nv_bfloat16 g_klo[(size_t)B_*H_*T_*DK_];
__device__ __nv_bfloat16 g_vhi[(size_t)B_*H_*T_*DK_];
__device__ __nv_bfloat16 g_vlo[(size_t)B_*H_*T_*DK_];
__device__ __nv_bfloat16 g_ohi[(size_t)M_*HD_];
__device__ __nv_bfloat16 g_olo[(size_t)M_*HD_];
__device__ __nv_bfloat16 g_xhi[(size_t)M_*KDIM];
__device__ __nv_bfloat16 g_xlo[(size_t)M_*KDIM];
__device__ __nv_bfloat16 g_whi[(size_t)4*KDIM*HD_];   // transposed [n][k]; z: q,k,v,o
__device__ __nv_bfloat16 g_wlo[(size_t)4*KDIM*HD_];

// ---------------- helpers ----------------
__device__ __forceinline__ uint32_t smem_u32(const void* p) {
    uint32_t a;
    asm("{ .reg .u64 t; cvta.to.shared.u64 t, %1; cvt.u32.u64 %0, t; }"
        : "=r"(a) : "l"(p));
    return a;
}
#define SW128(o) ((uint32_t)(o) ^ ((((uint32_t)(o)) >> 3) & 0x70u))

__device__ __forceinline__ void ldm_x4(uint32_t* r, uint32_t addr) {
    asm volatile("ldmatrix.sync.aligned.m8n8.x4.shared.b16 {%0,%1,%2,%3}, [%4];"
                 : "=r"(r[0]), "=r"(r[1]), "=r"(r[2]), "=r"(r[3]) : "r"(addr));
}
__device__ __forceinline__ void ldm_x4_trans(uint32_t* r, uint32_t addr) {
    asm volatile("ldmatrix.sync.aligned.m8n8.x4.trans.shared.b16 {%0,%1,%2,%3}, [%4];"
                 : "=r"(r[0]), "=r"(r[1]), "=r"(r[2]), "=r"(r[3]) : "r"(addr));
}

__device__ __forceinline__ void mma_bf16(float* c, const uint32_t* a,
                                         uint32_t b0, uint32_t b1) {
    asm volatile(
        "mma.sync.aligned.m16n8k16.row.col.f32.bf16.bf16.f32 "
        "{%0,%1,%2,%3}, {%4,%5,%6,%7}, {%8,%9}, {%0,%1,%2,%3};"
        : "+f"(c[0]), "+f"(c[1]), "+f"(c[2]), "+f"(c[3])
        : "r"(a[0]), "r"(a[1]), "r"(a[2]), "r"(a[3]), "r"(b0), "r"(b1));
}

__device__ __forceinline__ void cp_async16(uint32_t dst, const void* src) {
    asm volatile("cp.async.cg.shared.global [%0], [%1], 16;"
                 :: "r"(dst), "l"(src));
}
#define CP_COMMIT() asm volatile("cp.async.commit_group;" ::: "memory")
#define CP_WAIT0()  asm volatile("cp.async.wait_group 0;" ::: "memory")
#define CP_WAIT1()  asm volatile("cp.async.wait_group 1;" ::: "memory")

// rounding split (prep + gemm epilogue)
__device__ __forceinline__ void split2(float a, float b, uint32_t& hi, uint32_t& lo) {
    __nv_bfloat16 ah = __float2bfloat16(a);
    __nv_bfloat16 bh = __float2bfloat16(b);
    __nv_bfloat16 al = __float2bfloat16(a - __bfloat162float(ah));
    __nv_bfloat16 bl = __float2bfloat16(b - __bfloat162float(bh));
    uint16_t ahb = *(uint16_t*)&ah, bhb = *(uint16_t*)&bh;
    uint16_t alb = *(uint16_t*)&al, blb = *(uint16_t*)&bl;
    hi = (uint32_t)ahb | ((uint32_t)bhb << 16);
    lo = (uint32_t)alb | ((uint32_t)blb << 16);
}

// fast Dekker-style split (truncation hi, single packed cvt for lo)
__device__ __forceinline__ void fast_split2(float a, float b, uint32_t& hi, uint32_t& lo) {
    uint32_t ua = __float_as_uint(a) & 0xFFFF0000u;
    uint32_t ub = __float_as_uint(b) & 0xFFFF0000u;
    hi = __byte_perm(ua, ub, 0x7632);
    float la = a - __uint_as_float(ua);
    float lb = b - __uint_as_float(ub);
    asm("cvt.rn.bf16x2.f32 %0, %1, %2;" : "=r"(lo) : "f"(lb), "f"(la));
}

// ---------------- prep: merged convert + transpose (one launch) -----------
__global__ void __launch_bounds__(256)
prep_kernel(const float* __restrict__ x,
            const float* __restrict__ Wq, const float* __restrict__ Wk,
            const float* __restrict__ Wv, const float* __restrict__ Wo,
            __nv_bfloat16* __restrict__ xhi, __nv_bfloat16* __restrict__ xlo,
            __nv_bfloat16* __restrict__ whi, __nv_bfloat16* __restrict__ wlo)
{
    const int z = blockIdx.z;
    if (z == 4) {
        int base = (blockIdx.y * 32 + blockIdx.x) * 1024 + threadIdx.x;
#pragma unroll
        for (int p = 0; p < 4; p++) {
            int i = base + p * 256;
            float4 v = ((const float4*)x)[i];
            uint32_t h0, l0, h1, l1;
            split2(v.x, v.y, h0, l0);
            split2(v.z, v.w, h1, l1);
            ((uint2*)xhi)[i] = make_uint2(h0, h1);
            ((uint2*)xlo)[i] = make_uint2(l0, l1);
        }
        return;
    }
    __shared__ float t[32][33];
    const float* W = (z == 0) ? Wq : (z == 1) ? Wk : (z == 2) ? Wv : Wo;
    __nv_bfloat16* ho  = whi + (size_t)z * KDIM * HD_;
    __nv_bfloat16* lo_ = wlo + (size_t)z * KDIM * HD_;

    const int k0 = blockIdx.x * 32;
    const int n0 = blockIdx.y * 32;
    const int tx = threadIdx.x & 31, ty = threadIdx.x >> 5;

#pragma unroll
    for (int r = 0; r < 4; r++)
        t[ty + r * 8][tx] = W[(size_t)(k0 + ty + r * 8) * HD_ + n0 + tx];
    __syncthreads();
#pragma unroll
    for (int r = 0; r < 4; r++) {
        float f = t[tx][ty + r * 8];
        __nv_bfloat16 h = __float2bfloat16(f);
        __nv_bfloat16 l = __float2bfloat16(f - __bfloat162float(h));
        size_t o = (size_t)(n0 + ty + r * 8) * KDIM + k0 + tx;
        ho[o] = h;
        lo_[o] = l;
    }
}

// ---------------- bf16x3 mma.sync GEMM: 128x64 CTA, 2 CTAs/SM -------------
// 256 threads, 8 warps (4x2), warp tile 32x32, K chunks of 64.
// smem/buffer: A hi 16K, A lo 16K, B hi 8K, B lo 8K = 48KB; x2 = 96KB.
#define SM_AHI 0u
#define SM_ALO 16384u
#define SM_BHI 32768u
#define SM_BLO 40960u
#define SM_BUF 49152u
#define SM_TOTAL 98304

__device__ __forceinline__ void load_chunk(
    uint32_t sbuf,
    const __nv_bfloat16* __restrict__ Ahi, const __nv_bfloat16* __restrict__ Alo,
    const __nv_bfloat16* __restrict__ Bhi, const __nv_bfloat16* __restrict__ Blo,
    int bRow, int bCol, int ch, int tid)
{
    // A: 128 rows x 64 k (hi+lo)
#pragma unroll
    for (int p = 0; p < 4; p++) {
        int idx = p * 256 + tid;       // 0..1023
        int r = idx >> 3, c = idx & 7;
        uint32_t off = SW128(r * 128 + c * 16);
        size_t src = (size_t)(bRow * 128 + r) * KDIM + ch * 64 + c * 8;
        cp_async16(sbuf + SM_AHI + off, Ahi + src);
        cp_async16(sbuf + SM_ALO + off, Alo + src);
    }
    // B: 64 rows x 64 k (hi+lo)
#pragma unroll
    for (int p = 0; p < 2; p++) {
        int idx = p * 256 + tid;       // 0..511
        int r = idx >> 3, c = idx & 7;
        uint32_t off = SW128(r * 128 + c * 16);
        size_t src = (size_t)(bCol * 64 + r) * KDIM + ch * 64 + c * 8;
        cp_async16(sbuf + SM_BHI + off, Bhi + src);
        cp_async16(sbuf + SM_BLO + off, Blo + src);
    }
}

__global__ void __launch_bounds__(256, 2)
gemm_bf16_kernel(const __nv_bfloat16* __restrict__ Ahi,
                 const __nv_bfloat16* __restrict__ Alo,
                 __nv_bfloat16* __restrict__ S0h, __nv_bfloat16* __restrict__ S0l,
                 __nv_bfloat16* __restrict__ S1h, __nv_bfloat16* __restrict__ S1l,
                 __nv_bfloat16* __restrict__ S2h, __nv_bfloat16* __restrict__ S2l,
                 float* __restrict__ Cout,
                 int wzoff, int scatter)
{
    extern __shared__ char gsm[];
    const uint32_t sb = smem_u32(gsm);

    const int tid  = threadIdx.x;
    const int wid  = tid >> 5;
    const int lane = tid & 31;
    const int bRow = blockIdx.y;
    const int bCol = blockIdx.x;
    const int z    = blockIdx.z;

    const __nv_bfloat16* Bhi = g_whi + (size_t)(wzoff + z) * KDIM * HD_;
    const __nv_bfloat16* Blo = g_wlo + (size_t)(wzoff + z) * KDIM * HD_;

    const int m0 = (wid >> 1) * 32;    // 4 m-groups
    const int n0 = (wid & 1) * 32;     // 2 n-groups

    float acc[2][4][4];
#pragma unroll
    for (int mt = 0; mt < 2; mt++)
#pragma unroll
        for (int j = 0; j < 4; j++)
#pragma unroll
            for (int r = 0; r < 4; r++) acc[mt][j][r] = 0.0f;

    load_chunk(sb, Ahi, Alo, Bhi, Blo, bRow, bCol, 0, tid);
    CP_COMMIT();
    load_chunk(sb + SM_BUF, Ahi, Alo, Bhi, Blo, bRow, bCol, 1, tid);
    CP_COMMIT();

    for (int ch = 0; ch < NCH; ch++) {
        const uint32_t sbuf = sb + (ch & 1) * SM_BUF;
        if (ch == NCH - 1) CP_WAIT0(); else CP_WAIT1();
        __syncthreads();

#pragma unroll
        for (int ks = 0; ks < 4; ks++) {
            const uint32_t colb = ks * 32 + (lane >> 4) * 16;
            uint32_t ahi[2][4], alo[2][4], bhi4[2][4], blo4[2][4];
#pragma unroll
            for (int mt = 0; mt < 2; mt++) {
                uint32_t roff = (uint32_t)(m0 + mt * 16 + (lane & 15)) * 128 + colb;
                ldm_x4(ahi[mt], sbuf + SM_AHI + SW128(roff));
                ldm_x4(alo[mt], sbuf + SM_ALO + SW128(roff));
            }
#pragma unroll
            for (int nt = 0; nt < 2; nt++) {
                uint32_t roff = (uint32_t)(n0 + nt * 16 + (lane & 15)) * 128 + colb;
                ldm_x4(bhi4[nt], sbuf + SM_BHI + SW128(roff));
                ldm_x4(blo4[nt], sbuf + SM_BLO + SW128(roff));
            }
#pragma unroll
            for (int mt = 0; mt < 2; mt++)
#pragma unroll
                for (int j = 0; j < 4; j++)
                    mma_bf16(acc[mt][j], ahi[mt], bhi4[j >> 1][j & 1], bhi4[j >> 1][(j & 1) + 2]);
#pragma unroll
            for (int mt = 0; mt < 2; mt++)
#pragma unroll
                for (int j = 0; j < 4; j++)
                    mma_bf16(acc[mt][j], ahi[mt], blo4[j >> 1][j & 1], blo4[j >> 1][(j & 1) + 2]);
#pragma unroll
            for (int mt = 0; mt < 2; mt++)
#pragma unroll
                for (int j = 0; j < 4; j++)
                    mma_bf16(acc[mt][j], alo[mt], bhi4[j >> 1][j & 1], bhi4[j >> 1][(j & 1) + 2]);
        }
        __syncthreads();
        if (ch + 2 < NCH) {
            load_chunk(sbuf, Ahi, Alo, Bhi, Blo, bRow, bCol, ch + 2, tid);
            CP_COMMIT();
        }
    }

    if (scatter) {
        // staged epilogue: one head per bCol -> coalesced per-head block
        uint16_t* Dh = (uint16_t*)gsm;            // [128][64]
        uint16_t* Dl = (uint16_t*)(gsm + 16384);  // [128][64]
        const float sc = (z == 0) ? 8.0f : 1.0f;  // fold sqrt(dk) into q
#pragma unroll
        for (int mt = 0; mt < 2; mt++)
#pragma unroll
            for (int j = 0; j < 4; j++)
#pragma unroll
                for (int half = 0; half < 2; half++) {
                    int lrow = m0 + mt * 16 + (lane >> 2) + half * 8;
                    int lcol = n0 + j * 8 + (lane & 3) * 2;
                    uint32_t hi, lo;
                    split2(acc[mt][j][half * 2] * sc, acc[mt][j][half * 2 + 1] * sc, hi, lo);
                    *(uint32_t*)(Dh + lrow * 64 + lcol) = hi;
                    *(uint32_t*)(Dl + lrow * 64 + lcol) = lo;
                }
        __syncthreads();

        __nv_bfloat16* Gh = (z == 0) ? S0h : (z == 1) ? S1h : S2h;
        __nv_bfloat16* Gl = (z == 0) ? S0l : (z == 1) ? S1l : S2l;
        const int b  = bRow >> 4;
        const int t0 = (bRow & 15) * 128;
        const int h  = bCol;
        size_t base = ((size_t)(b * H_ + h) * T_ + t0) * DK_;
#pragma unroll
        for (int p = 0; p < 4; p++) {
            int idx = p * 256 + tid;       // 0..1023
            int r = idx >> 3, c = idx & 7;
            *(uint4*)(Gh + base + r * 64 + c * 8) = *(const uint4*)(Dh + r * 64 + c * 8);
            *(uint4*)(Gl + base + r * 64 + c * 8) = *(const uint4*)(Dl + r * 64 + c * 8);
        }
    } else {
        // fp32 output (final projection)
#pragma unroll
        for (int mt = 0; mt < 2; mt++)
#pragma unroll
            for (int j = 0; j < 4; j++) {
                int row = bRow * 128 + m0 + mt * 16 + (lane >> 2);
                int col = bCol * 64 + n0 + j * 8 + (lane & 3) * 2;
#pragma unroll
                for (int half = 0; half < 2; half++) {
                    int rr = row + half * 8;
                    *(float2*)(Cout + (size_t)rr * HD_ + col) =
                        make_float2(acc[mt][j][half * 2], acc[mt][j][half * 2 + 1]);
                }
            }
    }
}

// ---------------- flash attention on mma.sync (bf16x3, round-12 proven) ---
#define SM_QHI 0u
#define SM_QLO 16384u
#define SM_KV  32768u
#define KV_KHI 0u
#define KV_KLO 8192u
#define KV_VHI 16384u
#define KV_VLO 24576u
#define KV_STRIDE 32768u
#define FSM_TOTAL 98304

__device__ __forceinline__ void load_kv(
    uint32_t kvbuf, const __nv_bfloat16* kh, const __nv_bfloat16* kl,
    const __nv_bfloat16* vh, const __nv_bfloat16* vl, int j0, int tid)
{
#pragma unroll
    for (int p = 0; p < 2; p++) {
        int idx = p * 256 + tid;
        int r = idx >> 3;             // 0..63
        int c = idx & 7;
        uint32_t off = SW128(r * 128 + c * 16);
        size_t src = (size_t)(j0 + r) * DK_ + c * 8;
        cp_async16(kvbuf + KV_KHI + off, kh + src);
        cp_async16(kvbuf + KV_KLO + off, kl + src);
        cp_async16(kvbuf + KV_VHI + off, vh + src);
        cp_async16(kvbuf + KV_VLO + off, vl + src);
    }
}

__global__ void __launch_bounds__(256, 2)
flash_mma_kernel(const __nv_bfloat16* __restrict__ qhi, const __nv_bfloat16* __restrict__ qlo,
                 const __nv_bfloat16* __restrict__ khi, const __nv_bfloat16* __restrict__ klo,
                 const __nv_bfloat16* __restrict__ vhi, const __nv_bfloat16* __restrict__ vlo,
                 __nv_bfloat16* __restrict__ ohi, __nv_bfloat16* __restrict__ olo)
{
    extern __shared__ char fsm[];
    const uint32_t sb = smem_u32(fsm);
    const int tid  = threadIdx.x;
    const int w    = tid >> 5;
    const int lane = tid & 31;
    const int qt   = (gridDim.x - 1) - blockIdx.x;   // heavy tiles first
    const int bh   = blockIdx.y;
    const int i0   = qt * 128;

    const __nv_bfloat16* qh = qhi + (size_t)bh * T_ * DK_;
    const __nv_bfloat16* ql = qlo + (size_t)bh * T_ * DK_;
    const __nv_bfloat16* kh = khi + (size_t)bh * T_ * DK_;
    const __nv_bfloat16* kl = klo + (size_t)bh * T_ * DK_;
    const __nv_bfloat16* vh = vhi + (size_t)bh * T_ * DK_;
    const __nv_bfloat16* vl = vlo + (size_t)bh * T_ * DK_;

#pragma unroll
    for (int p = 0; p < 4; p++) {
        int idx = p * 256 + tid;
        int r = idx >> 3;
        int c = idx & 7;
        uint32_t off = SW128(r * 128 + c * 16);
        size_t src = (size_t)(i0 + r) * DK_ + c * 8;
        cp_async16(sb + SM_QHI + off, qh + src);
        cp_async16(sb + SM_QLO + off, ql + src);
    }
    CP_COMMIT();

    const int nkt = 2 * (qt + 1);
    load_kv(sb + SM_KV, kh, kl, vh, vl, 0, tid);
    CP_COMMIT();
    if (nkt > 1) {
        load_kv(sb + SM_KV + KV_STRIDE, kh, kl, vh, vl, 64, tid);
        CP_COMMIT();
    }

    float m_i[2] = {-1e30f, -1e30f};
    float l_i[2] = {0.0f, 0.0f};
    float o_acc[8][4];
#pragma unroll
    for (int f = 0; f < 8; f++)
#pragma unroll
        for (int r = 0; r < 4; r++) o_acc[f][r] = 0.0f;

    const int row0 = i0 + w * 16 + (lane >> 2);

    for (int jt = 0; jt < nkt; jt++) {
        const uint32_t kvbuf = sb + SM_KV + (uint32_t)(jt & 1) * KV_STRIDE;
        const int j0 = jt * 64;
        if (jt + 1 < nkt) CP_WAIT1(); else CP_WAIT0();
        __syncthreads();

        float s[8][4];
#pragma unroll
        for (int f = 0; f < 8; f++)
#pragma unroll
            for (int r = 0; r < 4; r++) s[f][r] = 0.0f;

#pragma unroll
        for (int ks = 0; ks < 4; ks++) {
            const uint32_t colb = ks * 32 + (lane >> 4) * 16;
            uint32_t aqh[4], aql[4];
            uint32_t roff = (uint32_t)(w * 16 + (lane & 15)) * 128 + colb;
            ldm_x4(aqh, sb + SM_QHI + SW128(roff));
            ldm_x4(aql, sb + SM_QLO + SW128(roff));
#pragma unroll
            for (int nt = 0; nt < 4; nt++) {
                uint32_t kh4[4], kl4[4];
                uint32_t noff = (uint32_t)(nt * 16 + (lane & 15)) * 128 + colb;
                ldm_x4(kh4, kvbuf + KV_KHI + SW128(noff));
                ldm_x4(kl4, kvbuf + KV_KLO + SW128(noff));
#pragma unroll
                for (int h = 0; h < 2; h++) {
                    int f = nt * 2 + h;
                    mma_bf16(s[f], aqh, kh4[h], kh4[h + 2]);
                    mma_bf16(s[f], aqh, kl4[h], kl4[h + 2]);
                    mma_bf16(s[f], aql, kh4[h], kh4[h + 2]);
                }
            }
        }

        if (j0 >= i0) {
#pragma unroll
            for (int f = 0; f < 8; f++) {
                int colg = j0 + f * 8 + (lane & 3) * 2;
                if (colg     > row0)     s[f][0] = -1e30f;
                if (colg + 1 > row0)     s[f][1] = -1e30f;
                if (colg     > row0 + 8) s[f][2] = -1e30f;
                if (colg + 1 > row0 + 8) s[f][3] = -1e30f;
            }
        }

#pragma unroll
        for (int half = 0; half < 2; half++) {
            float mn = -1e30f;
#pragma unroll
            for (int f = 0; f < 8; f++)
                mn = fmaxf(mn, fmaxf(s[f][half * 2], s[f][half * 2 + 1]));
            mn = fmaxf(mn, __shfl_xor_sync(0xffffffffu, mn, 1));
            mn = fmaxf(mn, __shfl_xor_sync(0xffffffffu, mn, 2));

            float mnew = fmaxf(m_i[half], mn);
            float corr = __expf(m_i[half] - mnew);
            m_i[half] = mnew;

            float rs = 0.0f;
#pragma unroll
            for (int f = 0; f < 8; f++) {
                float p0 = __expf(s[f][half * 2]     - mnew);
                float p1 = __expf(s[f][half * 2 + 1] - mnew);
                s[f][half * 2]     = p0;
                s[f][half * 2 + 1] = p1;
                rs += p0 + p1;
            }
            rs += __shfl_xor_sync(0xffffffffu, rs, 1);
            rs += __shfl_xor_sync(0xffffffffu, rs, 2);

            l_i[half] = l_i[half] * corr + rs;
#pragma unroll
            for (int f = 0; f < 8; f++) {
                o_acc[f][half * 2]     *= corr;
                o_acc[f][half * 2 + 1] *= corr;
            }
        }

#pragma unroll
        for (int ks = 0; ks < 4; ks++) {
            uint32_t ph[4], pl[4];
            fast_split2(s[2 * ks][0],     s[2 * ks][1],     ph[0], pl[0]);
            fast_split2(s[2 * ks][2],     s[2 * ks][3],     ph[1], pl[1]);
            fast_split2(s[2 * ks + 1][0], s[2 * ks + 1][1], ph[2], pl[2]);
            fast_split2(s[2 * ks + 1][2], s[2 * ks + 1][3], ph[3], pl[3]);
#pragma unroll
            for (int dt = 0; dt < 4; dt++) {
                uint32_t vh4[4], vl4[4];
                uint32_t voff = (uint32_t)(ks * 16 + (lane & 15)) * 128
                              + dt * 32 + (lane >> 4) * 16;
                ldm_x4_trans(vh4, kvbuf + KV_VHI + SW128(voff));
                ldm_x4_trans(vl4, kvbuf + KV_VLO + SW128(voff));
#pragma unroll
                for (int h = 0; h < 2; h++) {
                    int f = dt * 2 + h;
                    mma_bf16(o_acc[f], ph, vh4[h * 2], vh4[h * 2 + 1]);
                    mma_bf16(o_acc[f], ph, vl4[h * 2], vl4[h * 2 + 1]);
                    mma_bf16(o_acc[f], pl, vh4[h * 2], vh4[h * 2 + 1]);
                }
            }
        }
        __syncthreads();
        if (jt + 2 < nkt) {
            load_kv(kvbuf, kh, kl, vh, vl, (jt + 2) * 64, tid);
            CP_COMMIT();
        }
    }

    // staged O epilogue
    {
        uint16_t* Oh = (uint16_t*)fsm;
        uint16_t* Ol = (uint16_t*)(fsm + 16384);
        const float inv0 = 1.0f / l_i[0];
        const float inv1 = 1.0f / l_i[1];
        const int lr0 = w * 16 + (lane >> 2);
#pragma unroll
        for (int f = 0; f < 8; f++) {
            int d = f * 8 + (lane & 3) * 2;
            uint32_t hi, lo;
            fast_split2(o_acc[f][0] * inv0, o_acc[f][1] * inv0, hi, lo);
            *(uint32_t*)(Oh + lr0 * 64 + d) = hi;
            *(uint32_t*)(Ol + lr0 * 64 + d) = lo;
            fast_split2(o_acc[f][2] * inv1, o_acc[f][3] * inv1, hi, lo);
            *(uint32_t*)(Oh + (lr0 + 8) * 64 + d) = hi;
            *(uint32_t*)(Ol + (lr0 + 8) * 64 + d) = lo;
        }
        __syncthreads();

        const int b = bh >> 4, h = bh & 15;
        size_t base = ((size_t)(b * T_ + i0)) * HD_ + h * 64;
#pragma unroll
        for (int p = 0; p < 4; p++) {
            int idx = p * 256 + tid;
            int r = idx >> 3, c = idx & 7;
            *(uint4*)(ohi + base + (size_t)r * HD_ + c * 8) =
                *(const uint4*)(Oh + r * 64 + c * 8);
            *(uint4*)(olo + base + (size_t)r * HD_ + c * 8) =
                *(const uint4*)(Ol + r * 64 + c * 8);
        }
    }
}

// ---------------- launch ----------------
extern "C" void kernel_launch(void* const* d_in, const int* in_sizes, int n_in,
                              void* d_out, int out_size)
{
    const float* x  = (const float*)d_in[0];
    const float* qm = (const float*)d_in[1];
    const float* km = (const float*)d_in[2];
    const float* vm = (const float*)d_in[3];
    const float* wm = (const float*)d_in[4];
    float* out = (float*)d_out;

    __nv_bfloat16 *qhi, *qlo, *khi, *klo, *vhi, *vlo, *ohi, *olo, *xhi, *xlo, *whi, *wlo;
    cudaGetSymbolAddress((void**)&qhi, g_qhi);
    cudaGetSymbolAddress((void**)&qlo, g_qlo);
    cudaGetSymbolAddress((void**)&khi, g_khi);
    cudaGetSymbolAddress((void**)&klo, g_klo);
    cudaGetSymbolAddress((void**)&vhi, g_vhi);
    cudaGetSymbolAddress((void**)&vlo, g_vlo);
    cudaGetSymbolAddress((void**)&ohi, g_ohi);
    cudaGetSymbolAddress((void**)&olo, g_olo);
    cudaGetSymbolAddress((void**)&xhi, g_xhi);
    cudaGetSymbolAddress((void**)&xlo, g_xlo);
    cudaGetSymbolAddress((void**)&whi, g_whi);
    cudaGetSymbolAddress((void**)&wlo, g_wlo);

    cudaFuncSetAttribute(gemm_bf16_kernel, cudaFuncAttributeMaxDynamicSharedMemorySize, SM_TOTAL);
    cudaFuncSetAttribute(flash_mma_kernel, cudaFuncAttributeMaxDynamicSharedMemorySize, FSM_TOTAL);

    // merged prep
    dim3 pGrid(32, 32, 5);
    prep_kernel<<<pGrid, 256>>>(x, qm, km, vm, wm, xhi, xlo, whi, wlo);

    // fused QKV projection -> bf16 hi/lo splits in [B,H,T,DK] (q pre-scaled x8)
    dim3 qkvGrid(HD_ / 64, M_ / 128, 3);   // (16, 32, 3)
    gemm_bf16_kernel<<<qkvGrid, 256, SM_TOTAL>>>(
        xhi, xlo, qhi, qlo, khi, klo, vhi, vlo, (float*)0, 0, 1);

    // tensor-core causal flash -> bf16 hi/lo O in [B,T,H*DK]
    dim3 flashGrid(T_ / 128, B_ * H_);
    flash_mma_kernel<<<flashGrid, 256, FSM_TOTAL>>>(
        qhi, qlo, khi, klo, vhi, vlo, ohi, olo);

    // output projection (fp32 out)
    dim3 oGrid(HD_ / 64, M_ / 128, 1);     // (16, 32, 1)
    gemm_bf16_kernel<<<oGrid, 256, SM_TOTAL>>>(
        ohi, olo, (__nv_bfloat16*)0, (__nv_bfloat16*)0, (__nv_bfloat16*)0,
        (__nv_bfloat16*)0, (__nv_bfloat16*)0, (__nv_bfloat16*)0, out, 3, 0);
}

// round 17
// speedup vs baseline: 1.0979x; 1.0046x over previous
#include <cuda_runtime.h>
#include <cuda_bf16.h>
#include <stdint.h>
#include <math.h>

#define B_   2
#define T_   2048
#define C_   1024
#define H_   16
#define DK_  64
#define HD_  1024   // H_*DK_
#define M_   4096   // B_*T_
#define KDIM 1024
#define NCH  16     // KDIM / 64

// ---------------- scratch (no allocation allowed) ----------------
__device__ __nv_bfloat16 g_qhi[(size_t)B_*H_*T_*DK_];
__device__ __nv_bfloat16 g_qlo[(size_t)B_*H_*T_*DK_];
__device__ __nv_bfloat16 g_khi[(size_t)B_*H_*T_*DK_];
__device__ __nv_bfloat16 g_klo[(size_t)B_*H_*T_*DK_];
__device__ __nv_bfloat16 g_vhi[(size_t)B_*H_*T_*DK_];
__device__ __nv_bfloat16 g_vlo[(size_t)B_*H_*T_*DK_];
__device__ __nv_bfloat16 g_ohi[(size_t)M_*HD_];
__device__ __nv_bfloat16 g_olo[(size_t)M_*HD_];
__device__ __nv_bfloat16 g_xhi[(size_t)M_*KDIM];
__device__ __nv_bfloat16 g_xlo[(size_t)M_*KDIM];
__device__ __nv_bfloat16 g_whi[(size_t)4*KDIM*HD_];   // transposed [n][k]; z: q,k,v,o
__device__ __nv_bfloat16 g_wlo[(size_t)4*KDIM*HD_];

// ---------------- helpers ----------------
__device__ __forceinline__ uint32_t smem_u32(const void* p) {
    uint32_t a;
    asm("{ .reg .u64 t; cvta.to.shared.u64 t, %1; cvt.u32.u64 %0, t; }"
        : "=r"(a) : "l"(p));
    return a;
}
#define SW128(o) ((uint32_t)(o) ^ ((((uint32_t)(o)) >> 3) & 0x70u))

__device__ __forceinline__ void ldm_x4(uint32_t* r, uint32_t addr) {
    asm volatile("ldmatrix.sync.aligned.m8n8.x4.shared.b16 {%0,%1,%2,%3}, [%4];"
                 : "=r"(r[0]), "=r"(r[1]), "=r"(r[2]), "=r"(r[3]) : "r"(addr));
}
__device__ __forceinline__ void ldm_x4_trans(uint32_t* r, uint32_t addr) {
    asm volatile("ldmatrix.sync.aligned.m8n8.x4.trans.shared.b16 {%0,%1,%2,%3}, [%4];"
                 : "=r"(r[0]), "=r"(r[1]), "=r"(r[2]), "=r"(r[3]) : "r"(addr));
}

__device__ __forceinline__ void mma_bf16(float* c, const uint32_t* a,
                                         uint32_t b0, uint32_t b1) {
    asm volatile(
        "mma.sync.aligned.m16n8k16.row.col.f32.bf16.bf16.f32 "
        "{%0,%1,%2,%3}, {%4,%5,%6,%7}, {%8,%9}, {%0,%1,%2,%3};"
        : "+f"(c[0]), "+f"(c[1]), "+f"(c[2]), "+f"(c[3])
        : "r"(a[0]), "r"(a[1]), "r"(a[2]), "r"(a[3]), "r"(b0), "r"(b1));
}

__device__ __forceinline__ void cp_async16(uint32_t dst, const void* src) {
    asm volatile("cp.async.cg.shared.global [%0], [%1], 16;"
                 :: "r"(dst), "l"(src));
}
#define CP_COMMIT() asm volatile("cp.async.commit_group;" ::: "memory")
#define CP_WAIT0()  asm volatile("cp.async.wait_group 0;" ::: "memory")
#define CP_WAIT1()  asm volatile("cp.async.wait_group 1;" ::: "memory")

// rounding split (prep + gemm epilogue)
__device__ __forceinline__ void split2(float a, float b, uint32_t& hi, uint32_t& lo) {
    __nv_bfloat16 ah = __float2bfloat16(a);
    __nv_bfloat16 bh = __float2bfloat16(b);
    __nv_bfloat16 al = __float2bfloat16(a - __bfloat162float(ah));
    __nv_bfloat16 bl = __float2bfloat16(b - __bfloat162float(bh));
    uint16_t ahb = *(uint16_t*)&ah, bhb = *(uint16_t*)&bh;
    uint16_t alb = *(uint16_t*)&al, blb = *(uint16_t*)&bl;
    hi = (uint32_t)ahb | ((uint32_t)bhb << 16);
    lo = (uint32_t)alb | ((uint32_t)blb << 16);
}

// fast Dekker-style split (truncation hi, single packed cvt for lo)
__device__ __forceinline__ void fast_split2(float a, float b, uint32_t& hi, uint32_t& lo) {
    uint32_t ua = __float_as_uint(a) & 0xFFFF0000u;
    uint32_t ub = __float_as_uint(b) & 0xFFFF0000u;
    hi = __byte_perm(ua, ub, 0x7632);
    float la = a - __uint_as_float(ua);
    float lb = b - __uint_as_float(ub);
    asm("cvt.rn.bf16x2.f32 %0, %1, %2;" : "=r"(lo) : "f"(lb), "f"(la));
}

// ---------------- prep: merged convert + transpose (one launch) -----------
// z<4: transpose W_z in 64x64 tiles (only bx<16, by<16 active),
//      packed uint32 stores (full 128B sectors).
// z=4: elementwise x convert.
__global__ void __launch_bounds__(256)
prep_kernel(const float* __restrict__ x,
            const float* __restrict__ Wq, const float* __restrict__ Wk,
            const float* __restrict__ Wv, const float* __restrict__ Wo,
            __nv_bfloat16* __restrict__ xhi, __nv_bfloat16* __restrict__ xlo,
            __nv_bfloat16* __restrict__ whi, __nv_bfloat16* __restrict__ wlo)
{
    const int z = blockIdx.z;
    const int tid = threadIdx.x;
    if (z == 4) {
        int base = (blockIdx.y * 32 + blockIdx.x) * 1024 + tid;
#pragma unroll
        for (int p = 0; p < 4; p++) {
            int i = base + p * 256;
            float4 v = ((const float4*)x)[i];
            uint32_t h0, l0, h1, l1;
            split2(v.x, v.y, h0, l0);
            split2(v.z, v.w, h1, l1);
            ((uint2*)xhi)[i] = make_uint2(h0, h1);
            ((uint2*)xlo)[i] = make_uint2(l0, l1);
        }
        return;
    }
    if (blockIdx.x >= 16 || blockIdx.y >= 16) return;
    __shared__ float t[64][65];
    const float* W = (z == 0) ? Wq : (z == 1) ? Wk : (z == 2) ? Wv : Wo;
    __nv_bfloat16* ho  = whi + (size_t)z * KDIM * HD_;
    __nv_bfloat16* lo_ = wlo + (size_t)z * KDIM * HD_;

    const int k0 = blockIdx.x * 64;
    const int n0 = blockIdx.y * 64;

#pragma unroll
    for (int p = 0; p < 16; p++) {
        int idx = p * 256 + tid;
        int r = idx >> 6, c = idx & 63;
        t[r][c] = W[(size_t)(k0 + r) * HD_ + n0 + c];
    }
    __syncthreads();
#pragma unroll
    for (int p = 0; p < 8; p++) {
        int idx = p * 256 + tid;
        int n = idx >> 5, kp = idx & 31;
        float f0 = t[2 * kp][n];
        float f1 = t[2 * kp + 1][n];
        uint32_t h, l;
        split2(f0, f1, h, l);
        size_t o = (size_t)(n0 + n) * KDIM + k0 + 2 * kp;
        *(uint32_t*)(ho + o) = h;
        *(uint32_t*)(lo_ + o) = l;
    }
}

// ---------------- bf16x3 mma.sync GEMM: 128x64 CTA, 2 CTAs/SM -------------
// 256 threads, 8 warps (4x2), warp tile 32x32, K chunks of 64.
// Inner loop software-pipelines the hi-fragments across k16 steps.
#define SM_AHI 0u
#define SM_ALO 16384u
#define SM_BHI 32768u
#define SM_BLO 40960u
#define SM_BUF 49152u
#define SM_TOTAL 98304

__device__ __forceinline__ void load_chunk(
    uint32_t sbuf,
    const __nv_bfloat16* __restrict__ Ahi, const __nv_bfloat16* __restrict__ Alo,
    const __nv_bfloat16* __restrict__ Bhi, const __nv_bfloat16* __restrict__ Blo,
    int bRow, int bCol, int ch, int tid)
{
#pragma unroll
    for (int p = 0; p < 4; p++) {
        int idx = p * 256 + tid;
        int r = idx >> 3, c = idx & 7;
        uint32_t off = SW128(r * 128 + c * 16);
        size_t src = (size_t)(bRow * 128 + r) * KDIM + ch * 64 + c * 8;
        cp_async16(sbuf + SM_AHI + off, Ahi + src);
        cp_async16(sbuf + SM_ALO + off, Alo + src);
    }
#pragma unroll
    for (int p = 0; p < 2; p++) {
        int idx = p * 256 + tid;
        int r = idx >> 3, c = idx & 7;
        uint32_t off = SW128(r * 128 + c * 16);
        size_t src = (size_t)(bCol * 64 + r) * KDIM + ch * 64 + c * 8;
        cp_async16(sbuf + SM_BHI + off, Bhi + src);
        cp_async16(sbuf + SM_BLO + off, Blo + src);
    }
}

__global__ void __launch_bounds__(256, 2)
gemm_bf16_kernel(const __nv_bfloat16* __restrict__ Ahi,
                 const __nv_bfloat16* __restrict__ Alo,
                 __nv_bfloat16* __restrict__ S0h, __nv_bfloat16* __restrict__ S0l,
                 __nv_bfloat16* __restrict__ S1h, __nv_bfloat16* __restrict__ S1l,
                 __nv_bfloat16* __restrict__ S2h, __nv_bfloat16* __restrict__ S2l,
                 float* __restrict__ Cout,
                 int wzoff, int scatter)
{
    extern __shared__ char gsm[];
    const uint32_t sb = smem_u32(gsm);

    const int tid  = threadIdx.x;
    const int wid  = tid >> 5;
    const int lane = tid & 31;
    const int bRow = blockIdx.y;
    const int bCol = blockIdx.x;
    const int z    = blockIdx.z;

    const __nv_bfloat16* Bhi = g_whi + (size_t)(wzoff + z) * KDIM * HD_;
    const __nv_bfloat16* Blo = g_wlo + (size_t)(wzoff + z) * KDIM * HD_;

    const int m0 = (wid >> 1) * 32;
    const int n0 = (wid & 1) * 32;

    float acc[2][4][4];
#pragma unroll
    for (int mt = 0; mt < 2; mt++)
#pragma unroll
        for (int j = 0; j < 4; j++)
#pragma unroll
            for (int r = 0; r < 4; r++) acc[mt][j][r] = 0.0f;

    load_chunk(sb, Ahi, Alo, Bhi, Blo, bRow, bCol, 0, tid);
    CP_COMMIT();
    load_chunk(sb + SM_BUF, Ahi, Alo, Bhi, Blo, bRow, bCol, 1, tid);
    CP_COMMIT();

    for (int ch = 0; ch < NCH; ch++) {
        const uint32_t sbuf = sb + (ch & 1) * SM_BUF;
        if (ch == NCH - 1) CP_WAIT0(); else CP_WAIT1();
        __syncthreads();

        // hi-fragment double buffer across ks
        uint32_t ahiP[2][2][4], bhiP[2][2][4];
        {
            const uint32_t colb0 = (lane >> 4) * 16;
#pragma unroll
            for (int mt = 0; mt < 2; mt++)
                ldm_x4(ahiP[0][mt], sbuf + SM_AHI +
                       SW128((uint32_t)(m0 + mt * 16 + (lane & 15)) * 128 + colb0));
#pragma unroll
            for (int nt = 0; nt < 2; nt++)
                ldm_x4(bhiP[0][nt], sbuf + SM_BHI +
                       SW128((uint32_t)(n0 + nt * 16 + (lane & 15)) * 128 + colb0));
        }

#pragma unroll
        for (int ks = 0; ks < 4; ks++) {
            const int cur = ks & 1, nxt = cur ^ 1;
            const uint32_t colb = ks * 32 + (lane >> 4) * 16;

            // lo fragments for this ks (consumed after pass1 -> latency hidden)
            uint32_t alo[2][4], blo4[2][4];
#pragma unroll
            for (int mt = 0; mt < 2; mt++)
                ldm_x4(alo[mt], sbuf + SM_ALO +
                       SW128((uint32_t)(m0 + mt * 16 + (lane & 15)) * 128 + colb));
#pragma unroll
            for (int nt = 0; nt < 2; nt++)
                ldm_x4(blo4[nt], sbuf + SM_BLO +
                       SW128((uint32_t)(n0 + nt * 16 + (lane & 15)) * 128 + colb));

            // prefetch hi fragments for ks+1
            if (ks < 3) {
                const uint32_t colb2 = (ks + 1) * 32 + (lane >> 4) * 16;
#pragma unroll
                for (int mt = 0; mt < 2; mt++)
                    ldm_x4(ahiP[nxt][mt], sbuf + SM_AHI +
                           SW128((uint32_t)(m0 + mt * 16 + (lane & 15)) * 128 + colb2));
#pragma unroll
                for (int nt = 0; nt < 2; nt++)
                    ldm_x4(bhiP[nxt][nt], sbuf + SM_BHI +
                           SW128((uint32_t)(n0 + nt * 16 + (lane & 15)) * 128 + colb2));
            }

            // pass1: Ahi*Bhi (fragments prefetched -> no stall)
#pragma unroll
            for (int mt = 0; mt < 2; mt++)
#pragma unroll
                for (int j = 0; j < 4; j++)
                    mma_bf16(acc[mt][j], ahiP[cur][mt],
                             bhiP[cur][j >> 1][j & 1], bhiP[cur][j >> 1][(j & 1) + 2]);
            // pass2: Ahi*Blo
#pragma unroll
            for (int mt = 0; mt < 2; mt++)
#pragma unroll
                for (int j = 0; j < 4; j++)
                    mma_bf16(acc[mt][j], ahiP[cur][mt],
                             blo4[j >> 1][j & 1], blo4[j >> 1][(j & 1) + 2]);
            // pass3: Alo*Bhi
#pragma unroll
            for (int mt = 0; mt < 2; mt++)
#pragma unroll
                for (int j = 0; j < 4; j++)
                    mma_bf16(acc[mt][j], alo[mt],
                             bhiP[cur][j >> 1][j & 1], bhiP[cur][j >> 1][(j & 1) + 2]);
        }
        __syncthreads();
        if (ch + 2 < NCH) {
            load_chunk(sbuf, Ahi, Alo, Bhi, Blo, bRow, bCol, ch + 2, tid);
            CP_COMMIT();
        }
    }

    if (scatter) {
        uint16_t* Dh = (uint16_t*)gsm;            // [128][64]
        uint16_t* Dl = (uint16_t*)(gsm + 16384);  // [128][64]
        const float sc = (z == 0) ? 8.0f : 1.0f;  // fold sqrt(dk) into q
#pragma unroll
        for (int mt = 0; mt < 2; mt++)
#pragma unroll
            for (int j = 0; j < 4; j++)
#pragma unroll
                for (int half = 0; half < 2; half++) {
                    int lrow = m0 + mt * 16 + (lane >> 2) + half * 8;
                    int lcol = n0 + j * 8 + (lane & 3) * 2;
                    uint32_t hi, lo;
                    split2(acc[mt][j][half * 2] * sc, acc[mt][j][half * 2 + 1] * sc, hi, lo);
                    *(uint32_t*)(Dh + lrow * 64 + lcol) = hi;
                    *(uint32_t*)(Dl + lrow * 64 + lcol) = lo;
                }
        __syncthreads();

        __nv_bfloat16* Gh = (z == 0) ? S0h : (z == 1) ? S1h : S2h;
        __nv_bfloat16* Gl = (z == 0) ? S0l : (z == 1) ? S1l : S2l;
        const int b  = bRow >> 4;
        const int t0 = (bRow & 15) * 128;
        const int h  = bCol;
        size_t base = ((size_t)(b * H_ + h) * T_ + t0) * DK_;
#pragma unroll
        for (int p = 0; p < 4; p++) {
            int idx = p * 256 + tid;
            int r = idx >> 3, c = idx & 7;
            *(uint4*)(Gh + base + r * 64 + c * 8) = *(const uint4*)(Dh + r * 64 + c * 8);
            *(uint4*)(Gl + base + r * 64 + c * 8) = *(const uint4*)(Dl + r * 64 + c * 8);
        }
    } else {
#pragma unroll
        for (int mt = 0; mt < 2; mt++)
#pragma unroll
            for (int j = 0; j < 4; j++) {
                int row = bRow * 128 + m0 + mt * 16 + (lane >> 2);
                int col = bCol * 64 + n0 + j * 8 + (lane & 3) * 2;
#pragma unroll
                for (int half = 0; half < 2; half++) {
                    int rr = row + half * 8;
                    *(float2*)(Cout + (size_t)rr * HD_ + col) =
                        make_float2(acc[mt][j][half * 2], acc[mt][j][half * 2 + 1]);
                }
            }
    }
}

// ---------------- flash attention on mma.sync (bf16x3) ----------------
#define SM_QHI 0u
#define SM_QLO 16384u
#define SM_KV  32768u
#define KV_KHI 0u
#define KV_KLO 8192u
#define KV_VHI 16384u
#define KV_VLO 24576u
#define KV_STRIDE 32768u
#define FSM_TOTAL 98304

__device__ __forceinline__ void load_kv(
    uint32_t kvbuf, const __nv_bfloat16* kh, const __nv_bfloat16* kl,
    const __nv_bfloat16* vh, const __nv_bfloat16* vl, int j0, int tid)
{
#pragma unroll
    for (int p = 0; p < 2; p++) {
        int idx = p * 256 + tid;
        int r = idx >> 3;
        int c = idx & 7;
        uint32_t off = SW128(r * 128 + c * 16);
        size_t src = (size_t)(j0 + r) * DK_ + c * 8;
        cp_async16(kvbuf + KV_KHI + off, kh + src);
        cp_async16(kvbuf + KV_KLO + off, kl + src);
        cp_async16(kvbuf + KV_VHI + off, vh + src);
        cp_async16(kvbuf + KV_VLO + off, vl + src);
    }
}

__global__ void __launch_bounds__(256, 2)
flash_mma_kernel(const __nv_bfloat16* __restrict__ qhi, const __nv_bfloat16* __restrict__ qlo,
                 const __nv_bfloat16* __restrict__ khi, const __nv_bfloat16* __restrict__ klo,
                 const __nv_bfloat16* __restrict__ vhi, const __nv_bfloat16* __restrict__ vlo,
                 __nv_bfloat16* __restrict__ ohi, __nv_bfloat16* __restrict__ olo)
{
    extern __shared__ char fsm[];
    const uint32_t sb = smem_u32(fsm);
    const int tid  = threadIdx.x;
    const int w    = tid >> 5;
    const int lane = tid & 31;
    const int qt   = (gridDim.x - 1) - blockIdx.x;
    const int bh   = blockIdx.y;
    const int i0   = qt * 128;

    const __nv_bfloat16* qh = qhi + (size_t)bh * T_ * DK_;
    const __nv_bfloat16* ql = qlo + (size_t)bh * T_ * DK_;
    const __nv_bfloat16* kh = khi + (size_t)bh * T_ * DK_;
    const __nv_bfloat16* kl = klo + (size_t)bh * T_ * DK_;
    const __nv_bfloat16* vh = vhi + (size_t)bh * T_ * DK_;
    const __nv_bfloat16* vl = vlo + (size_t)bh * T_ * DK_;

#pragma unroll
    for (int p = 0; p < 4; p++) {
        int idx = p * 256 + tid;
        int r = idx >> 3;
        int c = idx & 7;
        uint32_t off = SW128(r * 128 + c * 16);
        size_t src = (size_t)(i0 + r) * DK_ + c * 8;
        cp_async16(sb + SM_QHI + off, qh + src);
        cp_async16(sb + SM_QLO + off, ql + src);
    }
    CP_COMMIT();

    const int nkt = 2 * (qt + 1);
    load_kv(sb + SM_KV, kh, kl, vh, vl, 0, tid);
    CP_COMMIT();
    if (nkt > 1) {
        load_kv(sb + SM_KV + KV_STRIDE, kh, kl, vh, vl, 64, tid);
        CP_COMMIT();
    }

    float m_i[2] = {-1e30f, -1e30f};
    float l_i[2] = {0.0f, 0.0f};
    float o_acc[8][4];
#pragma unroll
    for (int f = 0; f < 8; f++)
#pragma unroll
        for (int r = 0; r < 4; r++) o_acc[f][r] = 0.0f;

    const int row0 = i0 + w * 16 + (lane >> 2);
    const int wrow_max = i0 + w * 16 + 15;   // last q row owned by this warp

    for (int jt = 0; jt < nkt; jt++) {
        const uint32_t kvbuf = sb + SM_KV + (uint32_t)(jt & 1) * KV_STRIDE;
        const int j0 = jt * 64;
        if (jt + 1 < nkt) CP_WAIT1(); else CP_WAIT0();
        __syncthreads();

        // warp fully above the diagonal for this key tile -> P == 0, skip all
        if (j0 <= wrow_max) {
            float s[8][4];
#pragma unroll
            for (int f = 0; f < 8; f++)
#pragma unroll
                for (int r = 0; r < 4; r++) s[f][r] = 0.0f;

#pragma unroll
            for (int ks = 0; ks < 4; ks++) {
                const uint32_t colb = ks * 32 + (lane >> 4) * 16;
                uint32_t aqh[4], aql[4];
                uint32_t roff = (uint32_t)(w * 16 + (lane & 15)) * 128 + colb;
                ldm_x4(aqh, sb + SM_QHI + SW128(roff));
                ldm_x4(aql, sb + SM_QLO + SW128(roff));
#pragma unroll
                for (int nt = 0; nt < 4; nt++) {
                    uint32_t kh4[4], kl4[4];
                    uint32_t noff = (uint32_t)(nt * 16 + (lane & 15)) * 128 + colb;
                    ldm_x4(kh4, kvbuf + KV_KHI + SW128(noff));
                    ldm_x4(kl4, kvbuf + KV_KLO + SW128(noff));
#pragma unroll
                    for (int h = 0; h < 2; h++) {
                        int f = nt * 2 + h;
                        mma_bf16(s[f], aqh, kh4[h], kh4[h + 2]);
                        mma_bf16(s[f], aqh, kl4[h], kl4[h + 2]);
                        mma_bf16(s[f], aql, kh4[h], kh4[h + 2]);
                    }
                }
            }

            if (j0 >= i0) {
#pragma unroll
                for (int f = 0; f < 8; f++) {
                    int colg = j0 + f * 8 + (lane & 3) * 2;
                    if (colg     > row0)     s[f][0] = -1e30f;
                    if (colg + 1 > row0)     s[f][1] = -1e30f;
                    if (colg     > row0 + 8) s[f][2] = -1e30f;
                    if (colg + 1 > row0 + 8) s[f][3] = -1e30f;
                }
            }

#pragma unroll
            for (int half = 0; half < 2; half++) {
                float mn = -1e30f;
#pragma unroll
                for (int f = 0; f < 8; f++)
                    mn = fmaxf(mn, fmaxf(s[f][half * 2], s[f][half * 2 + 1]));
                mn = fmaxf(mn, __shfl_xor_sync(0xffffffffu, mn, 1));
                mn = fmaxf(mn, __shfl_xor_sync(0xffffffffu, mn, 2));

                float mnew = fmaxf(m_i[half], mn);
                float corr = __expf(m_i[half] - mnew);
                m_i[half] = mnew;

                float rs = 0.0f;
#pragma unroll
                for (int f = 0; f < 8; f++) {
                    float p0 = __expf(s[f][half * 2]     - mnew);
                    float p1 = __expf(s[f][half * 2 + 1] - mnew);
                    s[f][half * 2]     = p0;
                    s[f][half * 2 + 1] = p1;
                    rs += p0 + p1;
                }
                rs += __shfl_xor_sync(0xffffffffu, rs, 1);
                rs += __shfl_xor_sync(0xffffffffu, rs, 2);

                l_i[half] = l_i[half] * corr + rs;
#pragma unroll
                for (int f = 0; f < 8; f++) {
                    o_acc[f][half * 2]     *= corr;
                    o_acc[f][half * 2 + 1] *= corr;
                }
            }

#pragma unroll
            for (int ks = 0; ks < 4; ks++) {
                uint32_t ph[4], pl[4];
                fast_split2(s[2 * ks][0],     s[2 * ks][1],     ph[0], pl[0]);
                fast_split2(s[2 * ks][2],     s[2 * ks][3],     ph[1], pl[1]);
                fast_split2(s[2 * ks + 1][0], s[2 * ks + 1][1], ph[2], pl[2]);
                fast_split2(s[2 * ks + 1][2], s[2 * ks + 1][3], ph[3], pl[3]);
#pragma unroll
                for (int dt = 0; dt < 4; dt++) {
                    uint32_t vh4[4], vl4[4];
                    uint32_t voff = (uint32_t)(ks * 16 + (lane & 15)) * 128
                                  + dt * 32 + (lane >> 4) * 16;
                    ldm_x4_trans(vh4, kvbuf + KV_VHI + SW128(voff));
                    ldm_x4_trans(vl4, kvbuf + KV_VLO + SW128(voff));
#pragma unroll
                    for (int h = 0; h < 2; h++) {
                        int f = dt * 2 + h;
                        mma_bf16(o_acc[f], ph, vh4[h * 2], vh4[h * 2 + 1]);
                        mma_bf16(o_acc[f], ph, vl4[h * 2], vl4[h * 2 + 1]);
                        mma_bf16(o_acc[f], pl, vh4[h * 2], vh4[h * 2 + 1]);
                    }
                }
            }
        }
        __syncthreads();
        if (jt + 2 < nkt) {
            load_kv(kvbuf, kh, kl, vh, vl, (jt + 2) * 64, tid);
            CP_COMMIT();
        }
    }

    // staged O epilogue
    {
        uint16_t* Oh = (uint16_t*)fsm;
        uint16_t* Ol = (uint16_t*)(fsm + 16384);
        const float inv0 = 1.0f / l_i[0];
        const float inv1 = 1.0f / l_i[1];
        const int lr0 = w * 16 + (lane >> 2);
#pragma unroll
        for (int f = 0; f < 8; f++) {
            int d = f * 8 + (lane & 3) * 2;
            uint32_t hi, lo;
            fast_split2(o_acc[f][0] * inv0, o_acc[f][1] * inv0, hi, lo);
            *(uint32_t*)(Oh + lr0 * 64 + d) = hi;
            *(uint32_t*)(Ol + lr0 * 64 + d) = lo;
            fast_split2(o_acc[f][2] * inv1, o_acc[f][3] * inv1, hi, lo);
            *(uint32_t*)(Oh + (lr0 + 8) * 64 + d) = hi;
            *(uint32_t*)(Ol + (lr0 + 8) * 64 + d) = lo;
        }
        __syncthreads();

        const int b = bh >> 4, h = bh & 15;
        size_t base = ((size_t)(b * T_ + i0)) * HD_ + h * 64;
#pragma unroll
        for (int p = 0; p < 4; p++) {
            int idx = p * 256 + tid;
            int r = idx >> 3, c = idx & 7;
            *(uint4*)(ohi + base + (size_t)r * HD_ + c * 8) =
                *(const uint4*)(Oh + r * 64 + c * 8);
            *(uint4*)(olo + base + (size_t)r * HD_ + c * 8) =
                *(const uint4*)(Ol + r * 64 + c * 8);
        }
    }
}

// ---------------- launch ----------------
extern "C" void kernel_launch(void* const* d_in, const int* in_sizes, int n_in,
                              void* d_out, int out_size)
{
    const float* x  = (const float*)d_in[0];
    const float* qm = (const float*)d_in[1];
    const float* km = (const float*)d_in[2];
    const float* vm = (const float*)d_in[3];
    const float* wm = (const float*)d_in[4];
    float* out = (float*)d_out;

    __nv_bfloat16 *qhi, *qlo, *khi, *klo, *vhi, *vlo, *ohi, *olo, *xhi, *xlo, *whi, *wlo;
    cudaGetSymbolAddress((void**)&qhi, g_qhi);
    cudaGetSymbolAddress((void**)&qlo, g_qlo);
    cudaGetSymbolAddress((void**)&khi, g_khi);
    cudaGetSymbolAddress((void**)&klo, g_klo);
    cudaGetSymbolAddress((void**)&vhi, g_vhi);
    cudaGetSymbolAddress((void**)&vlo, g_vlo);
    cudaGetSymbolAddress((void**)&ohi, g_ohi);
    cudaGetSymbolAddress((void**)&olo, g_olo);
    cudaGetSymbolAddress((void**)&xhi, g_xhi);
    cudaGetSymbolAddress((void**)&xlo, g_xlo);
    cudaGetSymbolAddress((void**)&whi, g_whi);
    cudaGetSymbolAddress((void**)&wlo, g_wlo);

    cudaFuncSetAttribute(gemm_bf16_kernel, cudaFuncAttributeMaxDynamicSharedMemorySize, SM_TOTAL);
    cudaFuncSetAttribute(flash_mma_kernel, cudaFuncAttributeMaxDynamicSharedMemorySize, FSM_TOTAL);

    // merged prep
    dim3 pGrid(32, 32, 5);
    prep_kernel<<<pGrid, 256>>>(x, qm, km, vm, wm, xhi, xlo, whi, wlo);

    // fused QKV projection -> bf16 hi/lo splits in [B,H,T,DK] (q pre-scaled x8)
    dim3 qkvGrid(HD_ / 64, M_ / 128, 3);   // (16, 32, 3)
    gemm_bf16_kernel<<<qkvGrid, 256, SM_TOTAL>>>(
        xhi, xlo, qhi, qlo, khi, klo, vhi, vlo, (float*)0, 0, 1);

    // tensor-core causal flash -> bf16 hi/lo O in [B,T,H*DK]
    dim3 flashGrid(T_ / 128, B_ * H_);
    flash_mma_kernel<<<flashGrid, 256, FSM_TOTAL>>>(
        qhi, qlo, khi, klo, vhi, vlo, ohi, olo);

    // output projection (fp32 out)
    dim3 oGrid(HD_ / 64, M_ / 128, 1);     // (16, 32, 1)
    gemm_bf16_kernel<<<oGrid, 256, SM_TOTAL>>>(
        ohi, olo, (__nv_bfloat16*)0, (__nv_bfloat16*)0, (__nv_bfloat16*)0,
        (__nv_bfloat16*)0, (__nv_bfloat16*)0, (__nv_bfloat16*)0, out, 3, 0);
}